// round 8
// baseline (speedup 1.0000x reference)
#include <cuda_runtime.h>
#include <cuda_fp16.h>
#include <cstdint>

// ============================================================================
// out[t, k*512+c] = sum_b x[t, k*512+b] * blocks[k, b, c]
// 8 grouped GEMMs [16384,512]@[512,512], fp32 in/out.
//
// R8: CTA tile 128x512, 1024 threads = 32 warps (4M x 8N), warp tile 32x64.
// (R7 failed with exactly rel_err=sqrt(0.5): 512 threads = 16 warps covered
// only half the CTA tile; wn=wid>>2 spanned 0..3 not 0..7.)
// Single-pass FP16 mma.m16n8k16 (rel_err ~3e-4, calibrated R5/R6).
// x read exactly once from DRAM; quad-shuffle float4 epilogue.
// ============================================================================

#define NBLK   8
#define BLK    512
#define HIDDEN 4096
#define CTA_M  128
#define KC     64                  // K elems per chunk (128B fp16 rows)
#define NCH    (BLK / KC)          // 8
#define THREADS 1024

// smem stage: A 128x64 fp16 (16K) + B 512x64 fp16 (64K) = 80 KB; 2 stages
#define A_OFF 0
#define B_OFF 16384
#define STAGE_BYTES 81920
#define SMEM_TOTAL (2 * STAGE_BYTES)   // 160 KB

// SW128 swizzle for 128B rows: bits[6:4] ^= row bits[2:0]
#define SW(o) ((uint32_t)(o) ^ ((((uint32_t)(o)) >> 3) & 0x70))

// Pre-converted B operand scratch: [k][c][b] fp16 (transposed, K contiguous)
__device__ __align__(128) __half g_Bh[NBLK * BLK * BLK];

// ---------------------------------------------------------------- helpers
__device__ __forceinline__ uint32_t smem_to_u32(const void* p) {
    uint32_t a;
    asm("{ .reg .u64 t; cvta.to.shared.u64 t, %1; cvt.u32.u64 %0, t; }" : "=r"(a) : "l"(p));
    return a;
}

__device__ __forceinline__ void cp16(uint32_t dst, const void* src) {
    asm volatile("cp.async.cg.shared.global [%0], [%1], 16;" :: "r"(dst), "l"(src));
}
#define CP_COMMIT()  asm volatile("cp.async.commit_group;" ::: "memory")
#define CP_WAIT(N)   asm volatile("cp.async.wait_group %0;" :: "n"(N) : "memory")

__device__ __forceinline__ void ldm_x4(uint32_t* r, uint32_t addr) {
    asm volatile("ldmatrix.sync.aligned.m8n8.x4.shared.b16 {%0,%1,%2,%3}, [%4];"
                 : "=r"(r[0]), "=r"(r[1]), "=r"(r[2]), "=r"(r[3]) : "r"(addr));
}

__device__ __forceinline__ void mma16816(float* c, const uint32_t* a,
                                         uint32_t b0, uint32_t b1) {
    asm volatile(
        "mma.sync.aligned.m16n8k16.row.col.f32.f16.f16.f32 "
        "{%0,%1,%2,%3}, {%4,%5,%6,%7}, {%8,%9}, {%0,%1,%2,%3};"
        : "+f"(c[0]), "+f"(c[1]), "+f"(c[2]), "+f"(c[3])
        : "r"(a[0]), "r"(a[1]), "r"(a[2]), "r"(a[3]), "r"(b0), "r"(b1));
}

__device__ __forceinline__ uint32_t h2_as_u32(__half2 v) {
    uint32_t u; __builtin_memcpy(&u, &v, 4); return u;
}

// 8 fp32 -> 8 fp16 packed in a uint4
__device__ __forceinline__ uint4 cvt8(const float4& p, const float4& q) {
    uint4 r;
    r.x = h2_as_u32(__floats2half2_rn(p.x, p.y));
    r.y = h2_as_u32(__floats2half2_rn(p.z, p.w));
    r.z = h2_as_u32(__floats2half2_rn(q.x, q.y));
    r.w = h2_as_u32(__floats2half2_rn(q.z, q.w));
    return r;
}

// ---------------------------------------------------------------- prep kernel
// blocks[k][b][c] fp32 -> g_Bh[k][c][b] fp16 (transpose + convert)
__global__ void prep_B_kernel(const float* __restrict__ blocks) {
    __shared__ float t[32][33];
    int k = blockIdx.z;
    int c0 = blockIdx.x * 32;
    int b0 = blockIdx.y * 32;
    int tx = threadIdx.x, ty = threadIdx.y;
    #pragma unroll
    for (int j = ty; j < 32; j += 8)
        t[j][tx] = blocks[((size_t)k * BLK + b0 + j) * BLK + c0 + tx];
    __syncthreads();
    #pragma unroll
    for (int j = ty; j < 32; j += 8) {
        size_t o = ((size_t)k * BLK + c0 + j) * BLK + b0 + tx;
        g_Bh[o] = __float2half_rn(t[tx][j]);
    }
}

// ---------------------------------------------------------------- main kernel
__global__ void __launch_bounds__(THREADS, 1)
gemm_bd_kernel(const float* __restrict__ x, float* __restrict__ out, int mtiles) {
    extern __shared__ __align__(1024) char smem[];
    const uint32_t sb = smem_to_u32(smem);
    const int tid  = threadIdx.x;
    const int lane = tid & 31;
    const int wid  = tid >> 5;    // 0..31
    const int wm   = wid & 3;     // warp m-tile (32 rows), 4 groups
    const int wn   = wid >> 2;    // warp n-tile (64 cols), 8 groups

    const int bid   = blockIdx.x;
    const int mtile = bid % mtiles;           // fastest: CTAs of one kblk
    const int kblk  = bid / mtiles;           // share B in L2
    const int m0    = mtile * CTA_M;

    // ---- staging coords: 8 lanes cover one 128B smem row contiguously
    const int u = tid & 7;            // 16B unit within 128B row
    const int r = tid >> 3;           // row 0..127
    const uint32_t stA = SW(r * 128 + u * 16);
    uint32_t stB[4];
    #pragma unroll
    for (int p = 0; p < 4; p++)
        stB[p] = SW(((r & 127) + 128 * p) * 128 + u * 16);

    const float4* x4 = (const float4*)x;
    const size_t xrow = (size_t)(m0 + r) * (HIDDEN / 4);
    const int kb4 = kblk * (BLK / 4);   // float4 index; + ch*16 + u*2

    const __half* bptr[4];
    #pragma unroll
    for (int p = 0; p < 4; p++)
        bptr[p] = g_Bh + ((size_t)(kblk * BLK + r + 128 * p)) * BLK + u * 8;

    // ---- ldmatrix base offsets (UNswizzled; swizzle applied after +ko)
    const int lrow = lane & 15;
    const int lkh  = lane >> 4;
    uint32_t a_base[2], b_base[4];
    #pragma unroll
    for (int mh = 0; mh < 2; mh++)
        a_base[mh] = (uint32_t)((wm * 32 + mh * 16 + lrow) * 128 + lkh * 16);
    #pragma unroll
    for (int g = 0; g < 4; g++)
        b_base[g] = (uint32_t)((wn * 64 + g * 16 + lrow) * 128 + lkh * 16);

    float acc[2][8][4];
    #pragma unroll
    for (int mh = 0; mh < 2; mh++)
        #pragma unroll
        for (int nj = 0; nj < 8; nj++)
            #pragma unroll
            for (int i = 0; i < 4; i++) acc[mh][nj][i] = 0.f;

    float4 av[2];   // A fp32 prefetch (one row, 8 floats)

    // ---- A: LDG fp32 (coalesced) -> regs
    auto lda = [&](int ch) {
        int c4 = kb4 + ch * 16 + u * 2;
        av[0] = x4[xrow + c4];
        av[1] = x4[xrow + c4 + 1];
    };
    // ---- A: cvt fp16 -> smem (conflict-free)
    auto sta = [&](int slot) {
        char* s = smem + slot * STAGE_BYTES + A_OFF;
        *(uint4*)(s + stA) = cvt8(av[0], av[1]);
    };
    // ---- B: cp.async preconverted fp16 (4 row-passes of 128 rows)
    auto ldb = [&](int ch, int slot) {
        uint32_t s = sb + slot * STAGE_BYTES + B_OFF;
        #pragma unroll
        for (int p = 0; p < 4; p++)
            cp16(s + stB[p], bptr[p] + ch * KC);
    };
    // ---- compute one chunk: 4 k16-steps, single pass
    auto compute = [&](int slot) {
        uint32_t base = sb + slot * STAGE_BYTES;
        #pragma unroll
        for (int ks = 0; ks < 4; ks++) {
            uint32_t ko = (uint32_t)(ks * 32);
            uint32_t ah[2][4], bb[4][4];
            #pragma unroll
            for (int mh = 0; mh < 2; mh++)
                ldm_x4(ah[mh], base + A_OFF + SW(a_base[mh] + ko));
            #pragma unroll
            for (int g = 0; g < 4; g++)
                ldm_x4(bb[g], base + B_OFF + SW(b_base[g] + ko));
            #pragma unroll
            for (int mh = 0; mh < 2; mh++)
                #pragma unroll
                for (int nj = 0; nj < 8; nj++)
                    mma16816(acc[mh][nj], ah[mh],
                             bb[nj >> 1][nj & 1], bb[nj >> 1][(nj & 1) + 2]);
        }
    };

    // ---- prologue: fill stage 0
    lda(0); sta(0);
    ldb(0, 0); CP_COMMIT();

    // ---- main loop: 2-stage ping-pong, 1 sync per chunk
    #pragma unroll 1
    for (int ch = 0; ch < NCH; ch++) {
        const bool pf = (ch + 1) < NCH;
        if (pf) lda(ch + 1);             // LDG to regs (before sync)
        __syncthreads();                 // stage (ch+1)&1 free; stage ch&1 visible
        if (pf) {
            sta((ch + 1) & 1);
            ldb(ch + 1, (ch + 1) & 1); CP_COMMIT();
            CP_WAIT(1);                  // chunk ch's B arrived
        } else {
            CP_WAIT(0);
        }
        compute(ch & 1);
    }

    // ---- epilogue: quad-shuffle -> each lane stores float4 of one row
    const int t  = lane & 3;
    const int q  = lane >> 2;
    const int sbase = lane & ~3;
    const size_t ocol0 = (size_t)(kblk * BLK + wn * 64);
    #pragma unroll
    for (int mh = 0; mh < 2; mh++)
        #pragma unroll
        for (int h = 0; h < 2; h++) {
            int row = m0 + wm * 32 + mh * 16 + h * 8 + q;
            float* orow = out + (size_t)row * HIDDEN + ocol0;
            #pragma unroll
            for (int p = 0; p < 4; p++) {
                float2 E = make_float2(acc[mh][2 * p][2 * h], acc[mh][2 * p][2 * h + 1]);
                float2 O = make_float2(acc[mh][2 * p + 1][2 * h], acc[mh][2 * p + 1][2 * h + 1]);
                int s0 = sbase + ((2 * t) & 3);
                int s1 = sbase + ((2 * t + 1) & 3);
                float Eax = __shfl_sync(0xFFFFFFFFu, E.x, s0);
                float Eay = __shfl_sync(0xFFFFFFFFu, E.y, s0);
                float Ebx = __shfl_sync(0xFFFFFFFFu, E.x, s1);
                float Eby = __shfl_sync(0xFFFFFFFFu, E.y, s1);
                float Oax = __shfl_sync(0xFFFFFFFFu, O.x, s0);
                float Oay = __shfl_sync(0xFFFFFFFFu, O.y, s0);
                float Obx = __shfl_sync(0xFFFFFFFFu, O.x, s1);
                float Oby = __shfl_sync(0xFFFFFFFFu, O.y, s1);
                float4 v = (t < 2) ? make_float4(Eax, Eay, Ebx, Eby)
                                   : make_float4(Oax, Oay, Obx, Oby);
                __stcs((float4*)(orow + p * 16 + t * 4), v);
            }
        }
}

// ---------------------------------------------------------------- launch
extern "C" void kernel_launch(void* const* d_in, const int* in_sizes, int n_in,
                              void* d_out, int out_size) {
    const float* x      = (const float*)d_in[0];
    const float* blocks = (const float*)d_in[1];
    float* out          = (float*)d_out;

    int tokens = in_sizes[0] / HIDDEN;   // 16384
    int mtiles = tokens / CTA_M;         // 128

    cudaFuncSetAttribute(gemm_bd_kernel,
                         cudaFuncAttributeMaxDynamicSharedMemorySize, SMEM_TOTAL);

    // 1) transpose + fp16 convert of blocks (4 MB scratch, L2-resident)
    prep_B_kernel<<<dim3(BLK / 32, BLK / 32, NBLK), dim3(32, 8)>>>(blocks);

    // 2) grouped GEMM: one CTA per (mtile, kblk); mtile fastest so the 128
    //    CTAs of one kblk share its 512KB B slice in L2. x read exactly once.
    gemm_bd_kernel<<<mtiles * NBLK, THREADS, SMEM_TOTAL>>>(x, out, mtiles);
}